// round 1
// baseline (speedup 1.0000x reference)
#include <cuda_runtime.h>

typedef unsigned long long u64;

#define TT 50
#define EE 10

__device__ __forceinline__ u64 ffma2(u64 a, u64 b, u64 c){
    u64 d; asm("fma.rn.f32x2 %0, %1, %2, %3;" : "=l"(d) : "l"(a), "l"(b), "l"(c)); return d;
}
__device__ __forceinline__ u64 splat2(float v){
    u64 r; asm("mov.b64 %0, {%1, %1};" : "=l"(r) : "f"(v)); return r;
}
__device__ __forceinline__ void unpack2(u64 v, float& lo, float& hi){
    asm("mov.b64 {%0, %1}, %2;" : "=f"(lo), "=f"(hi) : "l"(v));
}
__device__ __forceinline__ float sigmoidf_fast(float v){
    return __fdividef(1.0f, 1.0f + __expf(-v));
}
__device__ __forceinline__ float tanhf_fast(float v){
    // tanh(x) = 1 - 2/(exp(2x)+1); exact at both saturations, ~1e-7 rel err
    return 1.0f - __fdividef(2.0f, __expf(2.0f * v) + 1.0f);
}

__device__ __forceinline__ void mac_row(u64 acc[5], const float* __restrict__ row, u64 s){
    const ulonglong2* p = (const ulonglong2*)row;   // 16B-aligned (rows padded to 16 floats)
    ulonglong2 w01 = p[0];                          // pairs (0,1),(2,3)
    ulonglong2 w23 = p[1];                          // pairs (4,5),(6,7)
    u64 w4 = *(const u64*)(row + 8);                // pair (8,9)
    acc[0] = ffma2(s, w01.x, acc[0]);
    acc[1] = ffma2(s, w01.y, acc[1]);
    acc[2] = ffma2(s, w23.x, acc[2]);
    acc[3] = ffma2(s, w23.y, acc[3]);
    acc[4] = ffma2(s, w4,    acc[4]);
}

__global__ void __launch_bounds__(256) augru_kernel(
    const float* __restrict__ X, const float* __restrict__ Aat,
    const float* __restrict__ h0,
    const float* __restrict__ Wi_r, const float* __restrict__ bi_r,
    const float* __restrict__ Wh_r, const float* __restrict__ Ws_r, const float* __restrict__ bs_r,
    const float* __restrict__ Wi_z, const float* __restrict__ bi_z,
    const float* __restrict__ Wh_z, const float* __restrict__ Ws_z, const float* __restrict__ bs_z,
    const float* __restrict__ Wi_h, const float* __restrict__ bi_h,
    const float* __restrict__ Wh_h, const float* __restrict__ Wt_h, const float* __restrict__ bt_h,
    float* __restrict__ out)
{
    // Fused matrices: sW[0]=Wi_r@Ws_r, sW[1]=Wh_r@Ws_r, sW[2]=Wi_z@Ws_z,
    //                 sW[3]=Wh_z@Ws_z, sW[4]=Wi_h@Wt_h, sW[5]=Wh_h@Wt_h
    // Rows padded to 16 floats for LDS.128 alignment.
    __shared__ __align__(16) float sW[6][160];
    __shared__ __align__(16) float sB[3][16];   // fused biases: b' = bs + bi@Ws
    __shared__ float sH0[16];

    {
        const float* W1[6] = {Wi_r, Wh_r, Wi_z, Wh_z, Wi_h, Wh_h};
        const float* W2[6] = {Ws_r, Ws_r, Ws_z, Ws_z, Wt_h, Wt_h};
        for (int idx = threadIdx.x; idx < 6 * 160; idx += blockDim.x){
            int m = idx / 160, r = idx % 160, i = r >> 4, j = r & 15;
            float v = 0.0f;
            if (j < EE){
                const float* a = W1[m]; const float* b2 = W2[m];
                #pragma unroll
                for (int k = 0; k < EE; k++) v = fmaf(a[i*EE + k], b2[k*EE + j], v);
            }
            sW[m][r] = v;
        }
        for (int idx = threadIdx.x; idx < 48; idx += blockDim.x){
            int g = idx >> 4, j = idx & 15;
            float v = 0.0f;
            if (j < EE){
                const float* bi = (g==0) ? bi_r : (g==1) ? bi_z : bi_h;
                const float* bs = (g==0) ? bs_r : (g==1) ? bs_z : bt_h;
                const float* Wg = (g==0) ? Ws_r : (g==1) ? Ws_z : Wt_h;
                v = bs[j];
                #pragma unroll
                for (int k = 0; k < EE; k++) v = fmaf(bi[k], Wg[k*EE + j], v);
            }
            sB[g][j] = v;
        }
        if (threadIdx.x < 16) sH0[threadIdx.x] = (threadIdx.x < EE) ? h0[threadIdx.x] : 0.0f;
    }
    __syncthreads();

    long b = (long)blockIdx.x * blockDim.x + threadIdx.x;
    const float* xp = X   + b * (TT * EE);
    const float* ap = Aat + b * (TT * EE);

    float h[EE];
    #pragma unroll
    for (int j = 0; j < EE; j++) h[j] = sH0[j];

    // double-buffered (x, a) loads: 40B per vector, 8B-aligned -> 5x float2
    float2 xb[5], ab[5];
    #pragma unroll
    for (int p = 0; p < 5; p++){
        xb[p] = *(const float2*)(xp + 2*p);
        ab[p] = *(const float2*)(ap + 2*p);
    }

    #pragma unroll 1
    for (int t = 0; t < TT; t++){
        int tn = (t + 1 < TT) ? (t + 1) : t;
        float2 xn[5], an[5];
        #pragma unroll
        for (int p = 0; p < 5; p++){
            xn[p] = *(const float2*)(xp + tn*EE + 2*p);
            an[p] = *(const float2*)(ap + tn*EE + 2*p);
        }

        float x[EE];
        #pragma unroll
        for (int p = 0; p < 5; p++){ x[2*p] = xb[p].x; x[2*p+1] = xb[p].y; }

        u64 accR[5], accZ[5], accH[5];
        #pragma unroll
        for (int p = 0; p < 5; p++){
            accR[p] = *(const u64*)&sB[0][2*p];
            accZ[p] = *(const u64*)&sB[1][2*p];
            accH[p] = *(const u64*)&sB[2][2*p];
        }

        // x contributions to all three gates (one splat serves 3 rows)
        #pragma unroll
        for (int i = 0; i < EE; i++){
            u64 sx = splat2(x[i]);
            mac_row(accR, &sW[0][i*16], sx);
            mac_row(accZ, &sW[2][i*16], sx);
            mac_row(accH, &sW[4][i*16], sx);
        }
        // h contributions to r and z
        #pragma unroll
        for (int i = 0; i < EE; i++){
            u64 sh = splat2(h[i]);
            mac_row(accR, &sW[1][i*16], sh);
            mac_row(accZ, &sW[3][i*16], sh);
        }

        float r[EE], g[EE];
        #pragma unroll
        for (int p = 0; p < 5; p++){
            float a0, a1; unpack2(accR[p], a0, a1);
            r[2*p]   = sigmoidf_fast(a0);
            r[2*p+1] = sigmoidf_fast(a1);
            float z0, z1; unpack2(accZ[p], z0, z1);
            g[2*p]   = h[2*p]   * sigmoidf_fast(z0);
            g[2*p+1] = h[2*p+1] * sigmoidf_fast(z1);
        }

        // (h*z) contribution to candidate
        #pragma unroll
        for (int i = 0; i < EE; i++){
            u64 sg = splat2(g[i]);
            mac_row(accH, &sW[5][i*16], sg);
        }

        // hc = tanh(...); Ra = a*r; h = (1-Ra)*h + Ra*hc
        #pragma unroll
        for (int p = 0; p < 5; p++){
            float c0, c1; unpack2(accH[p], c0, c1);
            float hc0 = tanhf_fast(c0);
            float hc1 = tanhf_fast(c1);
            float Ra0 = ab[p].x * r[2*p];
            float Ra1 = ab[p].y * r[2*p+1];
            h[2*p]   = h[2*p]   + Ra0 * (hc0 - h[2*p]);
            h[2*p+1] = h[2*p+1] + Ra1 * (hc1 - h[2*p+1]);
        }

        #pragma unroll
        for (int p = 0; p < 5; p++){ xb[p] = xn[p]; ab[p] = an[p]; }
    }

    #pragma unroll
    for (int p = 0; p < 5; p++){
        float2 o; o.x = h[2*p]; o.y = h[2*p+1];
        *(float2*)(out + b*EE + 2*p) = o;
    }
}

extern "C" void kernel_launch(void* const* d_in, const int* in_sizes, int n_in,
                              void* d_out, int out_size)
{
    const float* X   = (const float*)d_in[0];
    const float* Aat = (const float*)d_in[1];
    const float* h0  = (const float*)d_in[2];
    int Bn = in_sizes[0] / (TT * EE);   // 65536
    int threads = 256;
    int blocks = Bn / threads;          // 256 (B divisible by 256)
    augru_kernel<<<blocks, threads>>>(
        X, Aat, h0,
        (const float*)d_in[3],  (const float*)d_in[4],  (const float*)d_in[5],
        (const float*)d_in[6],  (const float*)d_in[7],
        (const float*)d_in[8],  (const float*)d_in[9],  (const float*)d_in[10],
        (const float*)d_in[11], (const float*)d_in[12],
        (const float*)d_in[13], (const float*)d_in[14], (const float*)d_in[15],
        (const float*)d_in[16], (const float*)d_in[17],
        (float*)d_out);
}